// round 2
// baseline (speedup 1.0000x reference)
#include <cuda_runtime.h>
#include <math.h>

#define HH 256
#define BM 64
#define BN 32
#define KT 32

// tree constants: B=8, D=7
static const int OFFS[7] = {0, 1, 9, 73, 585, 4681, 37449};
static const int SZS[7]  = {1, 8, 64, 512, 4096, 32768, 262144};

// scratch (device globals; no runtime allocation allowed)
__device__ float g_enc[299593 * 256];   // per-node encodings (same layout as ctx)
__device__ float g_hl0[262144 * 256];   // left-chain h ping (leaf-sized)
__device__ float g_hr0[262144 * 256];   // right-chain h ping
__device__ float g_hl1[32768 * 256];    // pong (only needed when T>1 -> n<=32768)
__device__ float g_hr1[32768 * 256];
__device__ float g_cl[32768 * 256];     // cell states (in-place safe)
__device__ float g_cr[32768 * 256];

__device__ __forceinline__ float sigf(float x) { return 1.0f / (1.0f + expf(-x)); }

// One LSTM time step for a batch of n sequences, fused GEMM + gates.
// x row for batch element i = X[(x_base + i*x_stride) * 256 ...]
// Tile: 64 rows x 32 h-cols x 4 gates. Thread: 8 rows x 1 col x 4 gates.
__global__ __launch_bounds__(256) void lstm_step_kernel(
    const float* __restrict__ X, int x_base, int x_stride,
    const float* __restrict__ Hin, const float* __restrict__ Cin,   // null on first step
    const float* __restrict__ Wih, const float* __restrict__ Whh,   // [1024,256] row-major
    const float* __restrict__ bih, const float* __restrict__ bhh,   // [1024]
    float* __restrict__ Hout, float* __restrict__ Cout,             // Cout null on last step
    int n)
{
    __shared__ float xs[BM][KT + 4];        // x or h tile (broadcast reads)
    __shared__ float ws[4][KT][BN + 1];     // weights: [gate][k][col] conflict-free

    const int tid  = threadIdx.x;
    const int col  = tid & 31;
    const int rg   = tid >> 5;              // 0..7 (8 warps)
    const int row0 = blockIdx.x * BM;
    const int cb   = blockIdx.y * BN;       // h-col base (blockIdx.y in 0..7)

    float acc[8][4];
#pragma unroll
    for (int r = 0; r < 8; r++)
#pragma unroll
        for (int g = 0; g < 4; g++) acc[r][g] = 0.f;

    const int npass = Hin ? 2 : 1;
    for (int pass = 0; pass < npass; pass++) {
        const float* __restrict__ W = pass ? Whh : Wih;
        for (int kt = 0; kt < HH; kt += KT) {
            // load 64x32 x/h tile (float4)
#pragma unroll
            for (int l = tid; l < BM * (KT / 4); l += 256) {
                int r = l >> 3, kq = l & 7;
                int grow = row0 + r;
                float4 v = make_float4(0.f, 0.f, 0.f, 0.f);
                if (grow < n) {
                    if (pass == 0)
                        v = *(const float4*)(X + (size_t)(x_base + grow * x_stride) * HH + kt + kq * 4);
                    else
                        v = *(const float4*)(Hin + (size_t)grow * HH + kt + kq * 4);
                }
                *(float4*)&xs[r][kq * 4] = v;
            }
            // load 4 gates x 32 cols x 32 k weight tile
#pragma unroll
            for (int l = tid; l < 4 * BN * (KT / 4); l += 256) {
                int kq = l & 7;
                int j  = (l >> 3) & 31;
                int g  = l >> 8;
                float4 v = *(const float4*)(W + (size_t)(g * HH + cb + j) * HH + kt + kq * 4);
                ws[g][kq * 4 + 0][j] = v.x;
                ws[g][kq * 4 + 1][j] = v.y;
                ws[g][kq * 4 + 2][j] = v.z;
                ws[g][kq * 4 + 3][j] = v.w;
            }
            __syncthreads();
#pragma unroll
            for (int kk = 0; kk < KT; kk++) {
                float xr[8], wv[4];
#pragma unroll
                for (int r = 0; r < 8; r++) xr[r] = xs[rg * 8 + r][kk];   // warp-uniform row -> broadcast
#pragma unroll
                for (int g = 0; g < 4; g++) wv[g] = ws[g][kk][col];       // consecutive -> conflict-free
#pragma unroll
                for (int r = 0; r < 8; r++)
#pragma unroll
                    for (int g = 0; g < 4; g++)
                        acc[r][g] = fmaf(xr[r], wv[g], acc[r][g]);
            }
            __syncthreads();
        }
    }

    // fused pointwise: torch gate order i, f, g, o
    const int jc = cb + col;
    float bsum[4];
#pragma unroll
    for (int g = 0; g < 4; g++) bsum[g] = bih[g * HH + jc] + bhh[g * HH + jc];

#pragma unroll
    for (int r = 0; r < 8; r++) {
        int grow = row0 + rg * 8 + r;
        if (grow < n) {
            float iv = sigf(acc[r][0] + bsum[0]);
            float fv = sigf(acc[r][1] + bsum[1]);
            float gv = tanhf(acc[r][2] + bsum[2]);
            float ov = sigf(acc[r][3] + bsum[3]);
            float cp = Cin ? Cin[(size_t)grow * HH + jc] : 0.f;
            float cn = fv * cp + iv * gv;
            float hn = ov * tanhf(cn);
            Hout[(size_t)grow * HH + jc] = hn;
            if (Cout) Cout[(size_t)grow * HH + jc] = cn;
        }
    }
}

// enc = tanh([el, er] @ Wenc^T + benc); Wenc [256, 512]
__global__ __launch_bounds__(256) void enc_kernel(
    const float* __restrict__ EL, const float* __restrict__ ER,
    const float* __restrict__ Wenc, const float* __restrict__ benc,
    float* __restrict__ out, int n)
{
    __shared__ float xs[BM][KT + 4];
    __shared__ float ws[KT][BN + 1];

    const int tid  = threadIdx.x;
    const int col  = tid & 31;
    const int rg   = tid >> 5;
    const int row0 = blockIdx.x * BM;
    const int cb   = blockIdx.y * BN;

    float acc[8];
#pragma unroll
    for (int r = 0; r < 8; r++) acc[r] = 0.f;

    for (int pass = 0; pass < 2; pass++) {
        const float* __restrict__ src = pass ? ER : EL;
        for (int kt = 0; kt < HH; kt += KT) {
#pragma unroll
            for (int l = tid; l < BM * (KT / 4); l += 256) {
                int r = l >> 3, kq = l & 7;
                int grow = row0 + r;
                float4 v = make_float4(0.f, 0.f, 0.f, 0.f);
                if (grow < n) v = *(const float4*)(src + (size_t)grow * HH + kt + kq * 4);
                *(float4*)&xs[r][kq * 4] = v;
            }
            {
                int kq = tid & 7, j = tid >> 3;   // 32 cols x 8 quads = 256 threads
                float4 v = *(const float4*)(Wenc + (size_t)(cb + j) * (2 * HH) + pass * HH + kt + kq * 4);
                ws[kq * 4 + 0][j] = v.x;
                ws[kq * 4 + 1][j] = v.y;
                ws[kq * 4 + 2][j] = v.z;
                ws[kq * 4 + 3][j] = v.w;
            }
            __syncthreads();
#pragma unroll
            for (int kk = 0; kk < KT; kk++) {
                float w = ws[kk][col];
#pragma unroll
                for (int r = 0; r < 8; r++)
                    acc[r] = fmaf(xs[rg * 8 + r][kk], w, acc[r]);
            }
            __syncthreads();
        }
    }
    int jc = cb + col;
    float b = benc[jc];
#pragma unroll
    for (int r = 0; r < 8; r++) {
        int grow = row0 + rg * 8 + r;
        if (grow < n) out[(size_t)grow * HH + jc] = tanhf(acc[r] + b);
    }
}

__global__ void copy_out_kernel(float* __restrict__ out) {
    out[threadIdx.x] = g_enc[threadIdx.x];
}

extern "C" void kernel_launch(void* const* d_in, const int* in_sizes, int n_in,
                              void* d_out, int out_size)
{
    const float* node_init = (const float*)d_in[0];
    const float* Wih_l = (const float*)d_in[1];
    const float* Whh_l = (const float*)d_in[2];
    const float* bih_l = (const float*)d_in[3];
    const float* bhh_l = (const float*)d_in[4];
    const float* Wih_r = (const float*)d_in[5];
    const float* Whh_r = (const float*)d_in[6];
    const float* bih_r = (const float*)d_in[7];
    const float* bhh_r = (const float*)d_in[8];
    const float* Wenc  = (const float*)d_in[9];
    const float* benc  = (const float*)d_in[10];

    float *enc, *hl0, *hr0, *hl1, *hr1, *cl, *cr;
    cudaGetSymbolAddress((void**)&enc, g_enc);
    cudaGetSymbolAddress((void**)&hl0, g_hl0);
    cudaGetSymbolAddress((void**)&hr0, g_hr0);
    cudaGetSymbolAddress((void**)&hl1, g_hl1);
    cudaGetSymbolAddress((void**)&hr1, g_hr1);
    cudaGetSymbolAddress((void**)&cl, g_cl);
    cudaGetSymbolAddress((void**)&cr, g_cr);

    for (int d = 6; d >= 0; d--) {
        int off = OFFS[d], n = SZS[d];
        dim3 grid((n + BM - 1) / BM, 8);
        if (d == 6) {
            // leaf: single step, zero initial state; final h always lands in *0 buffer
            lstm_step_kernel<<<grid, 256>>>(node_init, off, 1, nullptr, nullptr,
                                            Wih_l, Whh_l, bih_l, bhh_l, hl0, nullptr, n);
            lstm_step_kernel<<<grid, 256>>>(node_init, off, 1, nullptr, nullptr,
                                            Wih_r, Whh_r, bih_r, bhh_r, hr0, nullptr, n);
        } else {
            int coff = OFFS[d + 1];
            // left chain: child3, child2, child1, child0, own
            for (int t = 0; t < 5; t++) {
                const float* X; int xb, xst;
                if (t < 4) { X = enc; xb = coff + (3 - t); xst = 8; }
                else       { X = node_init; xb = off; xst = 1; }
                const float* Hi = (t == 0) ? nullptr : ((t & 1) ? hl0 : hl1);
                float* Ho = (t & 1) ? hl1 : hl0;              // T=5 -> last step writes hl0
                const float* Ci = (t == 0) ? nullptr : cl;
                float* Co = (t == 4) ? nullptr : cl;
                lstm_step_kernel<<<grid, 256>>>(X, xb, xst, Hi, Ci,
                                                Wih_l, Whh_l, bih_l, bhh_l, Ho, Co, n);
            }
            // right chain: own, child4, child5, child6, child7
            for (int t = 0; t < 5; t++) {
                const float* X; int xb, xst;
                if (t == 0) { X = node_init; xb = off; xst = 1; }
                else        { X = enc; xb = coff + (3 + t); xst = 8; }
                const float* Hi = (t == 0) ? nullptr : ((t & 1) ? hr0 : hr1);
                float* Ho = (t & 1) ? hr1 : hr0;
                const float* Ci = (t == 0) ? nullptr : cr;
                float* Co = (t == 4) ? nullptr : cr;
                lstm_step_kernel<<<grid, 256>>>(X, xb, xst, Hi, Ci,
                                                Wih_r, Whh_r, bih_r, bhh_r, Ho, Co, n);
            }
        }
        enc_kernel<<<grid, 256>>>(hl0, hr0, Wenc, benc, enc + (size_t)off * HH, n);
    }
    copy_out_kernel<<<1, 256>>>((float*)d_out);
}

// round 4
// speedup vs baseline: 1.9354x; 1.9354x over previous
#include <cuda_runtime.h>
#include <cuda_bf16.h>
#include <cstdint>
#include <math.h>

#define HH 256
static const int OFFS[7] = {0,1,9,73,585,4681,37449};
static const int SZS[7]  = {1,8,64,512,4096,32768,262144};
#define NTOT 299593

typedef uint32_t u32;

// packed bf16 pair: low16 = hi, high16 = lo
__device__ __forceinline__ u32 packsplit(float v){
    __nv_bfloat16 h = __float2bfloat16_rn(v);
    float r = v - __bfloat162float(h);
    __nv_bfloat16 l = __float2bfloat16_rn(r);
    return (u32)__bfloat16_as_ushort(h) | ((u32)__bfloat16_as_ushort(l) << 16);
}
__device__ __forceinline__ float unpackf(u32 p){
    return __bfloat162float(__ushort_as_bfloat16((unsigned short)(p & 0xffff)))
         + __bfloat162float(__ushort_as_bfloat16((unsigned short)(p >> 16)));
}
__device__ __forceinline__ float sigf(float x){ return 1.f/(1.f+expf(-x)); }
__device__ __forceinline__ u32 s2u(const void* p){
    u32 a; asm("{ .reg .u64 t; cvta.to.shared.u64 t, %1; cvt.u32.u64 %0, t; }" : "=r"(a) : "l"(p)); return a;
}
__device__ __forceinline__ void cpa16(u32 dst, const void* src, int ok){
    asm volatile("cp.async.cg.shared.global [%0], [%1], 16, %2;" :: "r"(dst), "l"(src), "r"(ok?16:0));
}
#define CP_COMMIT() asm volatile("cp.async.commit_group;" ::: "memory")
#define CP_WAIT1()  asm volatile("cp.async.wait_group 1;" ::: "memory")
#define CP_WAIT0()  asm volatile("cp.async.wait_group 0;" ::: "memory")
__device__ __forceinline__ void hmma(float* c, const u32* a, const u32* b){
    asm volatile("mma.sync.aligned.m16n8k16.row.col.f32.bf16.bf16.f32 "
      "{%0,%1,%2,%3}, {%4,%5,%6,%7}, {%8,%9}, {%0,%1,%2,%3};"
      : "+f"(c[0]),"+f"(c[1]),"+f"(c[2]),"+f"(c[3])
      : "r"(a[0]),"r"(a[1]),"r"(a[2]),"r"(a[3]), "r"(b[0]),"r"(b[1]));
}

// smem: 2 buffers x (A 128x36 u32 + B 128x36 u32)
#define PLANE 18432
#define BUF   36864
#define SMEMB 73728

// ---- device-global scratch (packed u32 activations) ----
__device__ __align__(16) u32 g_ni[NTOT*HH];
__device__ __align__(16) u32 g_en[NTOT*HH];
__device__ __align__(16) u32 g_l0[262144*HH], g_r0[262144*HH];
__device__ __align__(16) u32 g_l1[32768*HH],  g_r1[32768*HH];
__device__ __align__(16) float g_cl[32768*HH], g_cr[32768*HH];
__device__ __align__(16) u32 g_wxl[1024*HH], g_whl[1024*HH];
__device__ __align__(16) u32 g_wxr[1024*HH], g_whr[1024*HH];
__device__ __align__(16) u32 g_we[256*512];

// ---- loaders ----
__device__ __forceinline__ void ldA(u32 smA, const u32* __restrict__ src,
                                    int base, int stride, int koff, int row0, int n){
    int tid = threadIdx.x;
#pragma unroll
    for (int i=0;i<4;i++){
        int lin = tid + i*256;
        int row = lin>>3, kq = lin&7;
        int grow = row0+row;
        int ok = grow < n; if(!ok) grow = 0;
        cpa16(smA + (u32)(row*36 + kq*4)*4,
              src + (size_t)(base + grow*stride)*HH + koff + kq*4, ok);
    }
}
// lstm weights: col c -> W row (c&3)*256 + cb*32 + (c>>2)
__device__ __forceinline__ void ldBl(u32 smB, const u32* __restrict__ W, int cb, int koff){
    int tid = threadIdx.x;
#pragma unroll
    for (int i=0;i<4;i++){
        int lin = tid + i*256;
        int col = lin>>3, kq = lin&7;
        int wrow = (col&3)*HH + cb*32 + (col>>2);
        cpa16(smB + (u32)(col*36 + kq*4)*4, W + (size_t)wrow*HH + koff + kq*4, 1);
    }
}
// enc weights: W [256][512], row = cb*128+col
__device__ __forceinline__ void ldBe(u32 smB, const u32* __restrict__ W, int cb, int koff){
    int tid = threadIdx.x;
#pragma unroll
    for (int i=0;i<4;i++){
        int lin = tid + i*256;
        int col = lin>>3, kq = lin&7;
        cpa16(smB + (u32)(col*36 + kq*4)*4, W + (size_t)(cb*128+col)*512 + koff + kq*4, 1);
    }
}

__device__ __forceinline__ void comp(u32 smA, u32 smB, float (&acc)[4][4][4],
                                     int wm, int wn, int l){
#pragma unroll
    for (int ks=0; ks<32; ks+=16){
#pragma unroll
        for (int mt=0; mt<4; mt++){
            u32 ah[4], al[4];
#pragma unroll
            for (int q=0;q<4;q++){
                int r = wm*64 + mt*16 + (l>>2) + (q&1)*8;
                int c = ks + (l&3)*2 + (q>>1)*8;
                u32 p0, p1;
                asm volatile("ld.shared.v2.u32 {%0,%1}, [%2];" : "=r"(p0),"=r"(p1)
                    : "r"(smA + (u32)(r*36+c)*4));
                ah[q] = __byte_perm(p0,p1,0x5410);
                al[q] = __byte_perm(p0,p1,0x7632);
            }
#pragma unroll
            for (int nt=0; nt<4; nt++){
                u32 bh[2], bl[2];
#pragma unroll
                for (int q=0;q<2;q++){
                    int cc = wn*32 + nt*8 + (l>>2);
                    int k  = ks + (l&3)*2 + q*8;
                    u32 p0, p1;
                    asm volatile("ld.shared.v2.u32 {%0,%1}, [%2];" : "=r"(p0),"=r"(p1)
                        : "r"(smB + (u32)(cc*36+k)*4));
                    bh[q] = __byte_perm(p0,p1,0x5410);
                    bl[q] = __byte_perm(p0,p1,0x7632);
                }
                hmma(acc[mt][nt], ah, bh);
                hmma(acc[mt][nt], al, bh);
                hmma(acc[mt][nt], ah, bl);
            }
        }
    }
}

// ---- LSTM step: out = X@WxT + H@WhT -> gates -> c,h ----
__global__ void __launch_bounds__(256) lstm_mma(
    const u32* __restrict__ X, int xbase, int xstride,
    const u32* __restrict__ Hin,
    const u32* __restrict__ Wx, const u32* __restrict__ Wh,
    const float* __restrict__ bih, const float* __restrict__ bhh,
    const float* __restrict__ Cin, float* __restrict__ Cout,
    u32* __restrict__ Hout, int n)
{
    extern __shared__ char smc[];
    u32 smb = s2u(smc);
    __shared__ float bsm[128];
    int tid=threadIdx.x, l=tid&31, wid=tid>>5, wm=wid>>2, wn=wid&3;
    int row0 = blockIdx.x*128, cb = blockIdx.y;
    if (tid<128){
        int g=tid>>5, col=cb*32+(tid&31);
        bsm[tid] = bih[g*HH+col] + bhh[g*HH+col];
    }
    float acc[4][4][4];
#pragma unroll
    for(int a=0;a<4;a++)
#pragma unroll
    for(int b=0;b<4;b++)
#pragma unroll
    for(int q=0;q<4;q++) acc[a][b][q]=0.f;

    const int NCH = Hin ? 16 : 8;
#define ISSUE_L(ch, buf) do{ int _c=(ch); u32 _a=smb+(u32)(buf)*BUF, _b=_a+PLANE; \
    if(_c<8){ ldA(_a, X, xbase, xstride, _c*32, row0, n); ldBl(_b, Wx, cb, _c*32); } \
    else    { ldA(_a, Hin, 0, 1, (_c-8)*32, row0, n);     ldBl(_b, Wh, cb, (_c-8)*32); } \
    CP_COMMIT(); }while(0)

    ISSUE_L(0,0);
    for (int ch=0; ch<NCH; ch++){
        if (ch+1<NCH){ ISSUE_L(ch+1,(ch+1)&1); CP_WAIT1(); } else CP_WAIT0();
        __syncthreads();
        u32 a = smb + (u32)(ch&1)*BUF;
        comp(a, a+PLANE, acc, wm, wn, l);
        __syncthreads();
    }
#undef ISSUE_L

    bool odd = (l&1);
#pragma unroll
    for (int mt=0;mt<4;mt++)
#pragma unroll
    for (int nt=0;nt<4;nt++){
        float* c = acc[mt][nt];
        float s0 = odd ? c[0] : c[2];
        float s1 = odd ? c[1] : c[3];
        float t0 = __shfl_xor_sync(0xffffffffu, s0, 1);
        float t1 = __shfl_xor_sync(0xffffffffu, s1, 1);
        int hl = wn*8 + nt*2 + ((l&3)>>1);
        float iv = sigf ((odd? t0  : c[0]) + bsm[hl]);
        float fv = sigf ((odd? t1  : c[1]) + bsm[32+hl]);
        float gv = tanhf((odd? c[2]: t0 ) + bsm[64+hl]);
        float ov = sigf ((odd? c[3]: t1 ) + bsm[96+hl]);
        int grow = row0 + wm*64 + mt*16 + (l>>2) + (odd?8:0);
        if (grow < n){
            size_t e = (size_t)grow*HH + cb*32 + hl;
            float cp = Cin ? Cin[e] : 0.f;
            float cn = fv*cp + iv*gv;
            if (Cout) Cout[e] = cn;
            Hout[e] = packsplit(ov * tanhf(cn));
        }
    }
}

// ---- encoder: out = tanh([el,er]@WencT + benc) ----
__global__ void __launch_bounds__(256) enc_mma(
    const u32* __restrict__ EL, const u32* __restrict__ ER,
    const float* __restrict__ benc, u32* __restrict__ out, int n)
{
    extern __shared__ char smc[];
    u32 smb = s2u(smc);
    __shared__ float bsm[128];
    int tid=threadIdx.x, l=tid&31, wid=tid>>5, wm=wid>>2, wn=wid&3;
    int row0 = blockIdx.x*128, cb = blockIdx.y;
    if (tid<128) bsm[tid] = benc[cb*128+tid];
    float acc[4][4][4];
#pragma unroll
    for(int a=0;a<4;a++)
#pragma unroll
    for(int b=0;b<4;b++)
#pragma unroll
    for(int q=0;q<4;q++) acc[a][b][q]=0.f;

#define ISSUE_E(ch, buf) do{ int _c=(ch); u32 _a=smb+(u32)(buf)*BUF, _b=_a+PLANE; \
    if(_c<8) ldA(_a, EL, 0, 1, _c*32, row0, n); \
    else     ldA(_a, ER, 0, 1, (_c-8)*32, row0, n); \
    ldBe(_b, g_we, cb, _c*32); CP_COMMIT(); }while(0)

    ISSUE_E(0,0);
    for (int ch=0; ch<16; ch++){
        if (ch+1<16){ ISSUE_E(ch+1,(ch+1)&1); CP_WAIT1(); } else CP_WAIT0();
        __syncthreads();
        u32 a = smb + (u32)(ch&1)*BUF;
        comp(a, a+PLANE, acc, wm, wn, l);
        __syncthreads();
    }
#undef ISSUE_E

#pragma unroll
    for (int mt=0;mt<4;mt++)
#pragma unroll
    for (int nt=0;nt<4;nt++){
        float* c = acc[mt][nt];
        int col0 = wn*32 + nt*8 + (l&3)*2;
        int gcol = cb*128 + col0;
        int r0 = row0 + wm*64 + mt*16 + (l>>2);
        uint2 v0, v1;
        v0.x = packsplit(tanhf(c[0] + bsm[col0]));
        v0.y = packsplit(tanhf(c[1] + bsm[col0+1]));
        v1.x = packsplit(tanhf(c[2] + bsm[col0]));
        v1.y = packsplit(tanhf(c[3] + bsm[col0+1]));
        if (r0   < n) *(uint2*)(out + (size_t)r0*HH + gcol) = v0;
        if (r0+8 < n) *(uint2*)(out + (size_t)(r0+8)*HH + gcol) = v1;
    }
}

// ---- conversions ----
__global__ void convp(const float* __restrict__ s, u32* __restrict__ d, int n4){
    int i = blockIdx.x*256 + threadIdx.x;
    if (i >= n4) return;
    float4 v = ((const float4*)s)[i];
    uint4 o;
    o.x = packsplit(v.x); o.y = packsplit(v.y);
    o.z = packsplit(v.z); o.w = packsplit(v.w);
    ((uint4*)d)[i] = o;
}
__global__ void out_k(float* __restrict__ o){
    int t = threadIdx.x;
    o[t] = unpackf(g_en[t]);
}

extern "C" void kernel_launch(void* const* d_in, const int* in_sizes, int n_in,
                              void* d_out, int out_size)
{
    const float* ni   = (const float*)d_in[0];
    const float* Wihl = (const float*)d_in[1];
    const float* Whhl = (const float*)d_in[2];
    const float* bihl = (const float*)d_in[3];
    const float* bhhl = (const float*)d_in[4];
    const float* Wihr = (const float*)d_in[5];
    const float* Whhr = (const float*)d_in[6];
    const float* bihr = (const float*)d_in[7];
    const float* bhhr = (const float*)d_in[8];
    const float* Wenc = (const float*)d_in[9];
    const float* benc = (const float*)d_in[10];

    cudaFuncSetAttribute(lstm_mma, cudaFuncAttributeMaxDynamicSharedMemorySize, SMEMB);
    cudaFuncSetAttribute(enc_mma,  cudaFuncAttributeMaxDynamicSharedMemorySize, SMEMB);

    u32 *nip, *enp, *l0, *r0, *l1, *r1, *wxl, *whl, *wxr, *whr, *we;
    float *cl, *cr;
    cudaGetSymbolAddress((void**)&nip, g_ni);  cudaGetSymbolAddress((void**)&enp, g_en);
    cudaGetSymbolAddress((void**)&l0, g_l0);   cudaGetSymbolAddress((void**)&r0, g_r0);
    cudaGetSymbolAddress((void**)&l1, g_l1);   cudaGetSymbolAddress((void**)&r1, g_r1);
    cudaGetSymbolAddress((void**)&cl, g_cl);   cudaGetSymbolAddress((void**)&cr, g_cr);
    cudaGetSymbolAddress((void**)&wxl, g_wxl); cudaGetSymbolAddress((void**)&whl, g_whl);
    cudaGetSymbolAddress((void**)&wxr, g_wxr); cudaGetSymbolAddress((void**)&whr, g_whr);
    cudaGetSymbolAddress((void**)&we, g_we);

    convp<<<(NTOT*HH/4 + 255)/256, 256>>>(ni, nip, NTOT*HH/4);
    convp<<<256, 256>>>(Wihl, wxl, 1024*HH/4);
    convp<<<256, 256>>>(Whhl, whl, 1024*HH/4);
    convp<<<256, 256>>>(Wihr, wxr, 1024*HH/4);
    convp<<<256, 256>>>(Whhr, whr, 1024*HH/4);
    convp<<<128, 256>>>(Wenc, we, 256*512/4);

    for (int d = 6; d >= 0; d--) {
        int off = OFFS[d], n = SZS[d];
        dim3 grid((n + 127)/128, 8);
        if (d == 6) {
            lstm_mma<<<grid, 256, SMEMB>>>(nip, off, 1, nullptr, wxl, nullptr,
                bihl, bhhl, nullptr, nullptr, l0, n);
            lstm_mma<<<grid, 256, SMEMB>>>(nip, off, 1, nullptr, wxr, nullptr,
                bihr, bhhr, nullptr, nullptr, r0, n);
        } else {
            int coff = OFFS[d+1];
            for (int t = 0; t < 5; t++) {   // left: child3..0 then own
                const u32* X; int xb, xs;
                if (t < 4) { X = enp; xb = coff + (3 - t); xs = 8; }
                else       { X = nip; xb = off; xs = 1; }
                const u32* Hi = (t == 0) ? nullptr : ((t & 1) ? l0 : l1);
                u32* Ho = (t & 1) ? l1 : l0;
                lstm_mma<<<grid, 256, SMEMB>>>(X, xb, xs, Hi, wxl, whl,
                    bihl, bhhl, (t == 0) ? nullptr : cl, (t == 4) ? nullptr : cl, Ho, n);
            }
            for (int t = 0; t < 5; t++) {   // right: own then child4..7
                const u32* X; int xb, xs;
                if (t == 0) { X = nip; xb = off; xs = 1; }
                else        { X = enp; xb = coff + (3 + t); xs = 8; }
                const u32* Hi = (t == 0) ? nullptr : ((t & 1) ? r0 : r1);
                u32* Ho = (t & 1) ? r1 : r0;
                lstm_mma<<<grid, 256, SMEMB>>>(X, xb, xs, Hi, wxr, whr,
                    bihr, bhhr, (t == 0) ? nullptr : cr, (t == 4) ? nullptr : cr, Ho, n);
            }
        }
        enc_mma<<<dim3((n + 127)/128, 2), 256, SMEMB>>>(l0, r0, benc,
            enp + (size_t)off * HH, n);
    }
    out_k<<<1, 256>>>((float*)d_out);
}